// round 4
// baseline (speedup 1.0000x reference)
#include <cuda_runtime.h>
#include <math.h>

#define B_ 16
#define S_ 512
#define FRAME_ 438
#define D_ 800
#define H_ 8
#define DH_ 100
#define FFN_ 1024
#define HID_ 1024
#define POSE_ 274
#define WIN_ 100
#define M_ (B_*S_)
#define G4_ (4*HID_)
#define QT_ 8
#define KSPAN_ (2*WIN_+QT_)
#define KROW_ 101
#define NB_ 146

__device__ float g_x[M_*D_];
__device__ float g_q[M_*D_];
__device__ float g_k[M_*D_];
__device__ float g_v[M_*D_];
__device__ float g_o[M_*D_];
__device__ float g_r1[M_*D_];
__device__ float g_x2[M_*D_];
__device__ float g_h1[M_*FFN_];
__device__ float g_t2[M_*D_];
__device__ float g_enc[M_*D_];
__device__ float g_xwx[(size_t)M_*G4_];
__device__ float g_encp[M_*POSE_];
__device__ float g_hst[2][HID_*B_];
__device__ unsigned g_cnt;

enum { EPI_NONE=0, EPI_POS=1, EPI_ADD=2, EPI_BIAS_RELU=3, EPI_BIAS_ADD=4, EPI_BIAS=5 };

template<int EPI>
__global__ __launch_bounds__(256)
void gemm_k(const float* __restrict__ A, const float* __restrict__ W,
            float* __restrict__ C, int Mm, int Nn, int Kk,
            const float* __restrict__ bias, const float* __restrict__ addend,
            const float* __restrict__ pos_table, const int* __restrict__ pos_idx)
{
    __shared__ float As[16][129];
    __shared__ float Ws[16][128];
    int tid = threadIdx.x, tx = tid & 15, ty = tid >> 4;
    int rowBase = blockIdx.y * 128, colBase = blockIdx.x * 128;
    float acc[8][8];
#pragma unroll
    for (int i = 0; i < 8; i++)
#pragma unroll
        for (int j = 0; j < 8; j++) acc[i][j] = 0.f;

    for (int k0 = 0; k0 < Kk; k0 += 16) {
#pragma unroll
        for (int i = 0; i < 8; i++) {
            int idx = i*256 + tid, r = idx >> 4, c = idx & 15, gk = k0 + c;
            As[c][r] = (gk < Kk) ? A[(size_t)(rowBase+r)*Kk + gk] : 0.f;
        }
#pragma unroll
        for (int i = 0; i < 8; i++) {
            int idx = i*256 + tid, kk = idx >> 7, n = idx & 127;
            int gk = k0 + kk, gn = colBase + n;
            Ws[kk][n] = (gk < Kk && gn < Nn) ? W[(size_t)gk*Nn + gn] : 0.f;
        }
        __syncthreads();
#pragma unroll
        for (int kk = 0; kk < 16; kk++) {
            float a[8], w[8];
#pragma unroll
            for (int i = 0; i < 8; i++) a[i] = As[kk][ty + i*16];
#pragma unroll
            for (int j = 0; j < 8; j++) w[j] = Ws[kk][tx + j*16];
#pragma unroll
            for (int i = 0; i < 8; i++)
#pragma unroll
                for (int j = 0; j < 8; j++) acc[i][j] += a[i]*w[j];
        }
        __syncthreads();
    }
#pragma unroll
    for (int i = 0; i < 8; i++) {
        int m = rowBase + ty + i*16;
#pragma unroll
        for (int j = 0; j < 8; j++) {
            int n = colBase + tx + j*16;
            if (n < Nn) {
                float v = acc[i][j];
                if (EPI == EPI_POS)            v += bias[n] + pos_table[(size_t)pos_idx[m]*Nn + n];
                else if (EPI == EPI_ADD)       v += addend[(size_t)m*Nn + n];
                else if (EPI == EPI_BIAS_RELU) { v += bias[n]; v = v > 0.f ? v : 0.f; }
                else if (EPI == EPI_BIAS_ADD)  v += bias[n] + addend[(size_t)m*Nn + n];
                else if (EPI == EPI_BIAS)      v += bias[n];
                C[(size_t)m*Nn + n] = v;
            }
        }
    }
}

__global__ __launch_bounds__(256)
void ln_k(const float* __restrict__ in, float* __restrict__ out,
          const float* __restrict__ g, const float* __restrict__ b)
{
    __shared__ float buf[D_];
    __shared__ float red[256];
    int row = blockIdx.x, tid = threadIdx.x;
    float s = 0.f;
    for (int i = tid; i < D_; i += 256) { float v = in[(size_t)row*D_ + i]; buf[i] = v; s += v; }
    red[tid] = s; __syncthreads();
    for (int st = 128; st > 0; st >>= 1) { if (tid < st) red[tid] += red[tid+st]; __syncthreads(); }
    float mean = red[0] / (float)D_;
    __syncthreads();
    float ss = 0.f;
    for (int i = tid; i < D_; i += 256) { float d = buf[i]-mean; ss += d*d; }
    red[tid] = ss; __syncthreads();
    for (int st = 128; st > 0; st >>= 1) { if (tid < st) red[tid] += red[tid+st]; __syncthreads(); }
    float inv = rsqrtf(red[0]/(float)D_ + 1e-6f);
    for (int i = tid; i < D_; i += 256)
        out[(size_t)row*D_ + i] = (buf[i]-mean)*inv*g[i] + b[i];
}

__global__ __launch_bounds__(128)
void attn_k(const float* __restrict__ Q, const float* __restrict__ K,
            const float* __restrict__ V, float* __restrict__ O)
{
    extern __shared__ float ks[];
    __shared__ float qs[QT_*DH_];
    __shared__ float sc[QT_][KSPAN_];
    __shared__ float invs[QT_];
    int tid = threadIdx.x;
    int q0 = blockIdx.x * QT_, h = blockIdx.y, b = blockIdx.z;
    int kl = max(0, q0 - WIN_);
    int kh = min(S_-1, q0 + QT_-1 + WIN_);
    int nk = kh - kl + 1;
    size_t base = ((size_t)b*S_)*D_ + (size_t)h*DH_;

    for (int idx = tid; idx < QT_*DH_; idx += 128) {
        int qi = idx / DH_, dd = idx % DH_;
        qs[idx] = Q[base + (size_t)(q0+qi)*D_ + dd];
    }
    for (int idx = tid; idx < nk*DH_; idx += 128) {
        int kk = idx / DH_, dd = idx % DH_;
        ks[kk*KROW_ + dd] = K[base + (size_t)(kl+kk)*D_ + dd];
    }
    __syncthreads();

    for (int pid = tid; pid < QT_*nk; pid += 128) {
        int kk = pid % nk, qi = pid / nk;
        int qq = q0 + qi, kp = kl + kk;
        float v;
        if (kp >= qq - WIN_ && kp <= qq + WIN_) {
            float d = 0.f;
            for (int i = 0; i < DH_; i++) d += qs[qi*DH_ + i]*ks[kk*KROW_ + i];
            v = d * 0.1f;
        } else v = -1e30f;
        sc[qi][kk] = v;
    }
    __syncthreads();
    {
        int qi = tid >> 4, l = tid & 15;
        float m = -1e30f;
        for (int kk = l; kk < nk; kk += 16) m = fmaxf(m, sc[qi][kk]);
#pragma unroll
        for (int s2 = 8; s2 > 0; s2 >>= 1) m = fmaxf(m, __shfl_xor_sync(0xffffffffu, m, s2, 16));
        float ssum = 0.f;
        for (int kk = l; kk < nk; kk += 16) { float e = expf(sc[qi][kk]-m); sc[qi][kk] = e; ssum += e; }
#pragma unroll
        for (int s2 = 8; s2 > 0; s2 >>= 1) ssum += __shfl_xor_sync(0xffffffffu, ssum, s2, 16);
        if (l == 0) invs[qi] = 1.f / ssum;
    }
    __syncthreads();
    if (tid < DH_) {
        float acc[QT_];
#pragma unroll
        for (int qi = 0; qi < QT_; qi++) acc[qi] = 0.f;
        for (int kk = 0; kk < nk; kk++) {
            float vv = V[base + (size_t)(kl+kk)*D_ + tid];
#pragma unroll
            for (int qi = 0; qi < QT_; qi++) acc[qi] += sc[qi][kk]*vv;
        }
#pragma unroll
        for (int qi = 0; qi < QT_; qi++)
            O[base + (size_t)(q0+qi)*D_ + tid] = acc[qi]*invs[qi];
    }
}

__device__ __forceinline__ float sigf(float x){ return 1.f/(1.f+expf(-x)); }

__global__ void init_state_k(const float* __restrict__ vh, float* __restrict__ h1)
{
    int idx = blockIdx.x*256 + threadIdx.x;
    if (idx == 0) g_cnt = 0;
    if (idx < HID_*B_) {
        int b = idx / HID_, k = idx % HID_;
        h1[k*B_ + b] = vh[idx];
    }
}

#define ACC16(w,a0,a1,a2,a3) \
    acc[0]+=a0.x*(w); acc[1]+=a0.y*(w); acc[2]+=a0.z*(w); acc[3]+=a0.w*(w); \
    acc[4]+=a1.x*(w); acc[5]+=a1.y*(w); acc[6]+=a1.z*(w); acc[7]+=a1.w*(w); \
    acc[8]+=a2.x*(w); acc[9]+=a2.y*(w); acc[10]+=a2.z*(w); acc[11]+=a2.w*(w); \
    acc[12]+=a3.x*(w); acc[13]+=a3.y*(w); acc[14]+=a3.z*(w); acc[15]+=a3.w*(w);

__device__ __forceinline__ void gsync(unsigned& phase)
{
    __threadfence();               // release: h/out STGs visible before arrival
    __syncthreads();
    if (threadIdx.x == 0) {
        atomicAdd(&g_cnt, 1u);
        phase += NB_;
        while (*((volatile unsigned*)&g_cnt) < phase) __nanosleep(64);
    }
    __syncthreads();
}

// grid = 146 blocks: 0..127 gate-blocks (8 LSTM units each), 128..145 out-blocks.
// dynamic smem: hs 16384f | red 4096f | ps 4384f = 99456 bytes
__global__ __launch_bounds__(256)
void dec_persist_k(const float* __restrict__ Wx, const float* __restrict__ Wh,
                   const float* __restrict__ lb, const float* __restrict__ xwx,
                   const float* __restrict__ outW, const float* __restrict__ encp,
                   const float* __restrict__ vec_c, const float* __restrict__ dec0,
                   float* __restrict__ hbuf, float* __restrict__ outbuf,
                   const int* __restrict__ ep)
{
    extern __shared__ float sm[];
    float* hs  = sm;
    float* red = sm + 16384;
    float* ps  = sm + 20480;
    __shared__ float cs[128];
    int tid = threadIdx.x, bx = blockIdx.x;
    unsigned phase = 0;
    int p = (int)((double)(*ep) * 0.01);   // MUST be double: fp32 100*0.01 -> 0
    int per = p + 10;
    bool isGate = bx < 128;

    int u0 = bx * 8;
    int ci = tid & 31, ks8 = tid >> 5;
    int j = (ci >> 3)*1024 + u0 + (ci & 7);
    if (isGate && tid < 128) {
        int u3 = tid >> 4, b3 = tid & 15;
        cs[tid] = vec_c[b3*HID_ + u0 + u3];
    }
    int ob = bx - 128;
    int oci = tid & 15, oks = tid >> 4;
    int n0 = ob * 16;

#define OUT_PHASE(tt, hsrc) { \
        { float4* hv = (float4*)hs; const float4* h4 = (const float4*)(hsrc); \
          for (int i = tid; i < HID_*B_/4; i += 256) hv[i] = __ldcv(h4 + i); } \
        __syncthreads(); \
        float acc[16]; \
        _Pragma("unroll") for (int b = 0; b < 16; b++) acc[b] = 0.f; \
        int n = n0 + oci; \
        if (n < POSE_) { \
            const float4* h4s = (const float4*)hs; \
            int kb = oks*64; \
            _Pragma("unroll 4") for (int k = kb; k < kb+64; k++) { \
                float w = outW[(size_t)k*POSE_ + n]; \
                float4 a0=h4s[k*4+0],a1=h4s[k*4+1],a2=h4s[k*4+2],a3=h4s[k*4+3]; \
                ACC16(w,a0,a1,a2,a3); \
            } \
        } \
        _Pragma("unroll") for (int b = 0; b < 16; b++) red[(oks*16 + oci)*16 + b] = acc[b]; \
        __syncthreads(); \
        { int c2 = tid >> 4, b2 = tid & 15; int n2 = n0 + c2; \
          if (n2 < POSE_) { \
            float s = 0.f; \
            _Pragma("unroll") for (int kq = 0; kq < 16; kq++) s += red[(kq*16 + c2)*16 + b2]; \
            size_t off = ((size_t)b2*S_ + (tt))*POSE_ + n2; \
            outbuf[off] = s + encp[off]; } } \
    }

    for (int t = 0; t < S_; t++) {
        bool sampled = (t % per) < p;
        const float* hr = hbuf + (size_t)((t+1)&1)*(HID_*B_);
        float*       hw = hbuf + (size_t)(t&1)*(HID_*B_);

        if (sampled && t > 0) {          // out_{t-1} must land before gates_t reads it
            if (!isGate) OUT_PHASE(t-1, hr);
            gsync(phase);
        }

        if (isGate) {
            { float4* hv = (float4*)hs; const float4* h4 = (const float4*)hr;
              for (int i = tid; i < HID_*B_/4; i += 256) hv[i] = __ldcv(h4 + i); }
            if (sampled) {
                for (int i = tid; i < POSE_*B_; i += 256) {
                    int kk = i >> 4, bb = i & 15;
                    const float* src = (t == 0) ? (dec0 + bb*POSE_ + kk)
                                                : (outbuf + ((size_t)bb*S_ + (t-1))*POSE_ + kk);
                    ps[i] = __ldcv(src);
                }
            }
            __syncthreads();

            float acc[16];
#pragma unroll
            for (int b = 0; b < 16; b++) acc[b] = 0.f;
            const float4* h4 = (const float4*)hs;
            int kbeg = ks8*128, kend = kbeg + 128;
#pragma unroll 4
            for (int k = kbeg; k < kend; k++) {
                float w = Wh[(size_t)k*G4_ + j];
                float4 a0=h4[k*4+0],a1=h4[k*4+1],a2=h4[k*4+2],a3=h4[k*4+3];
                ACC16(w,a0,a1,a2,a3);
            }
            if (sampled) {
                const float4* p4 = (const float4*)ps;
                int s2 = ks8*35, e2 = min(POSE_, s2+35);
                for (int k = s2; k < e2; k++) {
                    float w = Wx[(size_t)k*G4_ + j];
                    float4 a0=p4[k*4+0],a1=p4[k*4+1],a2=p4[k*4+2],a3=p4[k*4+3];
                    ACC16(w,a0,a1,a2,a3);
                }
            }
#pragma unroll
            for (int b = 0; b < 16; b++) red[((ks8<<5) + ci)*16 + b] = acc[b];
            __syncthreads();

            for (int pi = tid; pi < 512; pi += 256) {
                int c2 = pi >> 4, b2 = pi & 15;
                float s = 0.f;
#pragma unroll
                for (int kq = 0; kq < 8; kq++) s += red[((kq<<5) + c2)*16 + b2];
                int j2 = (c2 >> 3)*1024 + u0 + (c2 & 7);
                s += lb[j2];
                if (!sampled) s += xwx[((size_t)b2*S_ + t)*G4_ + j2];
                ps[c2*16 + b2] = s;
            }
            __syncthreads();

            if (tid < 128) {
                int u3 = tid >> 4, b3 = tid & 15;
                float vi = ps[(0*8+u3)*16 + b3];
                float vf = ps[(1*8+u3)*16 + b3];
                float vg = ps[(2*8+u3)*16 + b3];
                float vo = ps[(3*8+u3)*16 + b3];
                float c = cs[tid];
                c = sigf(vf)*c + sigf(vi)*tanhf(vg);
                float h = sigf(vo)*tanhf(c);
                cs[tid] = c;
                hw[(u0 + u3)*16 + b3] = h;
            }
        } else {
            if (t > 0 && !sampled) OUT_PHASE(t-1, hr);
        }
        gsync(phase);
    }
    if (!isGate) {
        const float* hlast = hbuf + (size_t)((S_-1)&1)*(HID_*B_);
        OUT_PHASE(S_-1, hlast);
    }
#undef OUT_PHASE
}

extern "C" void kernel_launch(void* const* d_in, const int* in_sizes, int n_in,
                              void* d_out, int out_size)
{
    (void)in_sizes; (void)n_in; (void)out_size;
    const float* src_seq = (const float*)d_in[0];
    const int*   src_pos = (const int*)  d_in[1];
    const float* tgt_seq = (const float*)d_in[2];
    const float* vec_h   = (const float*)d_in[3];
    const float* vec_c   = (const float*)d_in[4];
    const float* dec0    = (const float*)d_in[5];
    const float* emb_W   = (const float*)d_in[6];
    const float* emb_b   = (const float*)d_in[7];
    const float* pos_t   = (const float*)d_in[8];
    const float* Wq      = (const float*)d_in[9];
    const float* Wk      = (const float*)d_in[10];
    const float* Wv      = (const float*)d_in[11];
    const float* Wo      = (const float*)d_in[12];
    const float* ln1g    = (const float*)d_in[13];
    const float* ln1b    = (const float*)d_in[14];
    const float* fW1     = (const float*)d_in[15];
    const float* fb1     = (const float*)d_in[16];
    const float* fW2     = (const float*)d_in[17];
    const float* fb2     = (const float*)d_in[18];
    const float* ln2g    = (const float*)d_in[19];
    const float* ln2b    = (const float*)d_in[20];
    const float* lWx     = (const float*)d_in[21];
    const float* lWh     = (const float*)d_in[22];
    const float* lb      = (const float*)d_in[23];
    const float* outW    = (const float*)d_in[24];
    const float* outb    = (const float*)d_in[25];
    const int*   ep      = (const int*)  d_in[26];
    float* out = (float*)d_out;

    void *px,*pq,*pk,*pv,*po,*pr1,*px2,*ph1,*pt2,*penc,*pxwx,*pencp,*phst;
    cudaGetSymbolAddress(&px,  g_x);   cudaGetSymbolAddress(&pq,  g_q);
    cudaGetSymbolAddress(&pk,  g_k);   cudaGetSymbolAddress(&pv,  g_v);
    cudaGetSymbolAddress(&po,  g_o);   cudaGetSymbolAddress(&pr1, g_r1);
    cudaGetSymbolAddress(&px2, g_x2);  cudaGetSymbolAddress(&ph1, g_h1);
    cudaGetSymbolAddress(&pt2, g_t2);  cudaGetSymbolAddress(&penc,g_enc);
    cudaGetSymbolAddress(&pxwx,g_xwx); cudaGetSymbolAddress(&pencp,g_encp);
    cudaGetSymbolAddress(&phst,g_hst);
    float *X=(float*)px, *Qb=(float*)pq, *Kb=(float*)pk, *Vb=(float*)pv, *Ob=(float*)po;
    float *R1=(float*)pr1, *X2=(float*)px2, *H1=(float*)ph1, *T2=(float*)pt2, *ENC=(float*)penc;
    float *XWX=(float*)pxwx, *ENCP=(float*)pencp, *HST=(float*)phst;

    cudaFuncSetAttribute(attn_k,        cudaFuncAttributeMaxDynamicSharedMemorySize, KSPAN_*KROW_*4);
    cudaFuncSetAttribute(dec_persist_k, cudaFuncAttributeMaxDynamicSharedMemorySize, 99456);

    dim3 gD((D_+127)/128, M_/128), gF((FFN_+127)/128, M_/128);
    dim3 gG4((G4_+127)/128, M_/128), gP((POSE_+127)/128, M_/128);

    // encoder
    gemm_k<EPI_POS><<<gD,256>>>(src_seq, emb_W, X, M_, D_, FRAME_, emb_b, nullptr, pos_t, src_pos);
    gemm_k<EPI_NONE><<<gD,256>>>(X, Wq, Qb, M_, D_, D_, nullptr, nullptr, nullptr, nullptr);
    gemm_k<EPI_NONE><<<gD,256>>>(X, Wk, Kb, M_, D_, D_, nullptr, nullptr, nullptr, nullptr);
    gemm_k<EPI_NONE><<<gD,256>>>(X, Wv, Vb, M_, D_, D_, nullptr, nullptr, nullptr, nullptr);
    attn_k<<<dim3(S_/QT_, H_, B_),128,KSPAN_*KROW_*4>>>(Qb, Kb, Vb, Ob);
    gemm_k<EPI_ADD><<<gD,256>>>(Ob, Wo, R1, M_, D_, D_, nullptr, X, nullptr, nullptr);
    ln_k<<<M_,256>>>(R1, X2, ln1g, ln1b);
    gemm_k<EPI_BIAS_RELU><<<gF,256>>>(X2, fW1, H1, M_, FFN_, D_, fb1, nullptr, nullptr, nullptr);
    gemm_k<EPI_BIAS_ADD><<<gD,256>>>(H1, fW2, T2, M_, D_, FFN_, fb2, X2, nullptr, nullptr);
    ln_k<<<M_,256>>>(T2, ENC, ln2g, ln2b);

    // decoder precompute
    gemm_k<EPI_NONE><<<gG4,256>>>(tgt_seq, lWx, XWX, M_, G4_, POSE_, nullptr, nullptr, nullptr, nullptr);
    gemm_k<EPI_BIAS><<<gP,256>>>(ENC, outW + (size_t)HID_*POSE_, ENCP, M_, POSE_, D_, outb, nullptr, nullptr, nullptr);
    init_state_k<<<(HID_*B_+255)/256,256>>>(vec_h, HST + HID_*B_);

    // one persistent kernel: all 512 LSTM steps + output projections
    dec_persist_k<<<NB_,256,99456>>>(lWx, lWh, lb, XWX, outW, ENCP,
                                     vec_c, dec0, HST, out, ep);
}

// round 5
// speedup vs baseline: 1.0263x; 1.0263x over previous
#include <cuda_runtime.h>
#include <cuda_bf16.h>
#include <math.h>

#define B_ 16
#define S_ 512
#define FRAME_ 438
#define D_ 800
#define H_ 8
#define DH_ 100
#define FFN_ 1024
#define HID_ 1024
#define POSE_ 274
#define WIN_ 100
#define M_ (B_*S_)
#define G4_ (4*HID_)
#define QT_ 8
#define KSPAN_ (2*WIN_+QT_)
#define KROW_ 101
#define GATEB_ 128
#define OUTB_ 18
#define NB_ (GATEB_+OUTB_)
#define HBW_ 516          // words per h row (1032 halves: 1024 + 8 pad)
#define HBTOT_ (16*HBW_)  // 8256 words per h buffer
#define XBW_ 148          // words per x row (296 halves: 288 + 8 pad)
#define OGRP_ 35          // ceil(274/8)

__device__ float g_x[M_*D_];
__device__ float g_q[M_*D_];
__device__ float g_k[M_*D_];
__device__ float g_v[M_*D_];
__device__ float g_o[M_*D_];
__device__ float g_r1[M_*D_];
__device__ float g_x2[M_*D_];
__device__ float g_h1[M_*FFN_];
__device__ float g_t2[M_*D_];
__device__ float g_enc[M_*D_];
__device__ float g_xwx[(size_t)M_*G4_];
__device__ float g_encp[M_*POSE_];
__device__ __align__(16) unsigned g_hb[2*HBTOT_];
__device__ uint2 g_whb[(size_t)GATEB_*4*64*32];
__device__ uint2 g_wxb[(size_t)GATEB_*4*18*32];
__device__ uint2 g_owb[(size_t)OGRP_*64*32];
__device__ unsigned g_cnt;

enum { EPI_NONE=0, EPI_POS=1, EPI_ADD=2, EPI_BIAS_RELU=3, EPI_BIAS_ADD=4, EPI_BIAS=5 };

template<int EPI>
__global__ __launch_bounds__(256)
void gemm_k(const float* __restrict__ A, const float* __restrict__ W,
            float* __restrict__ C, int Mm, int Nn, int Kk,
            const float* __restrict__ bias, const float* __restrict__ addend,
            const float* __restrict__ pos_table, const int* __restrict__ pos_idx)
{
    __shared__ float As[16][129];
    __shared__ float Ws[16][128];
    int tid = threadIdx.x, tx = tid & 15, ty = tid >> 4;
    int rowBase = blockIdx.y * 128, colBase = blockIdx.x * 128;
    float acc[8][8];
#pragma unroll
    for (int i = 0; i < 8; i++)
#pragma unroll
        for (int j = 0; j < 8; j++) acc[i][j] = 0.f;

    for (int k0 = 0; k0 < Kk; k0 += 16) {
#pragma unroll
        for (int i = 0; i < 8; i++) {
            int idx = i*256 + tid, r = idx >> 4, c = idx & 15, gk = k0 + c;
            As[c][r] = (gk < Kk) ? A[(size_t)(rowBase+r)*Kk + gk] : 0.f;
        }
#pragma unroll
        for (int i = 0; i < 8; i++) {
            int idx = i*256 + tid, kk = idx >> 7, n = idx & 127;
            int gk = k0 + kk, gn = colBase + n;
            Ws[kk][n] = (gk < Kk && gn < Nn) ? W[(size_t)gk*Nn + gn] : 0.f;
        }
        __syncthreads();
#pragma unroll
        for (int kk = 0; kk < 16; kk++) {
            float a[8], w[8];
#pragma unroll
            for (int i = 0; i < 8; i++) a[i] = As[kk][ty + i*16];
#pragma unroll
            for (int j = 0; j < 8; j++) w[j] = Ws[kk][tx + j*16];
#pragma unroll
            for (int i = 0; i < 8; i++)
#pragma unroll
                for (int j = 0; j < 8; j++) acc[i][j] += a[i]*w[j];
        }
        __syncthreads();
    }
#pragma unroll
    for (int i = 0; i < 8; i++) {
        int m = rowBase + ty + i*16;
#pragma unroll
        for (int j = 0; j < 8; j++) {
            int n = colBase + tx + j*16;
            if (n < Nn) {
                float v = acc[i][j];
                if (EPI == EPI_POS)            v += bias[n] + pos_table[(size_t)pos_idx[m]*Nn + n];
                else if (EPI == EPI_ADD)       v += addend[(size_t)m*Nn + n];
                else if (EPI == EPI_BIAS_RELU) { v += bias[n]; v = v > 0.f ? v : 0.f; }
                else if (EPI == EPI_BIAS_ADD)  v += bias[n] + addend[(size_t)m*Nn + n];
                else if (EPI == EPI_BIAS)      v += bias[n];
                C[(size_t)m*Nn + n] = v;
            }
        }
    }
}

__global__ __launch_bounds__(256)
void ln_k(const float* __restrict__ in, float* __restrict__ out,
          const float* __restrict__ g, const float* __restrict__ b)
{
    __shared__ float buf[D_];
    __shared__ float red[256];
    int row = blockIdx.x, tid = threadIdx.x;
    float s = 0.f;
    for (int i = tid; i < D_; i += 256) { float v = in[(size_t)row*D_ + i]; buf[i] = v; s += v; }
    red[tid] = s; __syncthreads();
    for (int st = 128; st > 0; st >>= 1) { if (tid < st) red[tid] += red[tid+st]; __syncthreads(); }
    float mean = red[0] / (float)D_;
    __syncthreads();
    float ss = 0.f;
    for (int i = tid; i < D_; i += 256) { float d = buf[i]-mean; ss += d*d; }
    red[tid] = ss; __syncthreads();
    for (int st = 128; st > 0; st >>= 1) { if (tid < st) red[tid] += red[tid+st]; __syncthreads(); }
    float inv = rsqrtf(red[0]/(float)D_ + 1e-6f);
    for (int i = tid; i < D_; i += 256)
        out[(size_t)row*D_ + i] = (buf[i]-mean)*inv*g[i] + b[i];
}

__global__ __launch_bounds__(128)
void attn_k(const float* __restrict__ Q, const float* __restrict__ K,
            const float* __restrict__ V, float* __restrict__ O)
{
    extern __shared__ float ks[];
    __shared__ float qs[QT_*DH_];
    __shared__ float sc[QT_][KSPAN_];
    __shared__ float invs[QT_];
    int tid = threadIdx.x;
    int q0 = blockIdx.x * QT_, h = blockIdx.y, b = blockIdx.z;
    int kl = max(0, q0 - WIN_);
    int kh = min(S_-1, q0 + QT_-1 + WIN_);
    int nk = kh - kl + 1;
    size_t base = ((size_t)b*S_)*D_ + (size_t)h*DH_;

    for (int idx = tid; idx < QT_*DH_; idx += 128) {
        int qi = idx / DH_, dd = idx % DH_;
        qs[idx] = Q[base + (size_t)(q0+qi)*D_ + dd];
    }
    for (int idx = tid; idx < nk*DH_; idx += 128) {
        int kk = idx / DH_, dd = idx % DH_;
        ks[kk*KROW_ + dd] = K[base + (size_t)(kl+kk)*D_ + dd];
    }
    __syncthreads();

    for (int pid = tid; pid < QT_*nk; pid += 128) {
        int kk = pid % nk, qi = pid / nk;
        int qq = q0 + qi, kp = kl + kk;
        float v;
        if (kp >= qq - WIN_ && kp <= qq + WIN_) {
            float d = 0.f;
            for (int i = 0; i < DH_; i++) d += qs[qi*DH_ + i]*ks[kk*KROW_ + i];
            v = d * 0.1f;
        } else v = -1e30f;
        sc[qi][kk] = v;
    }
    __syncthreads();
    {
        int qi = tid >> 4, l = tid & 15;
        float m = -1e30f;
        for (int kk = l; kk < nk; kk += 16) m = fmaxf(m, sc[qi][kk]);
#pragma unroll
        for (int s2 = 8; s2 > 0; s2 >>= 1) m = fmaxf(m, __shfl_xor_sync(0xffffffffu, m, s2, 16));
        float ssum = 0.f;
        for (int kk = l; kk < nk; kk += 16) { float e = expf(sc[qi][kk]-m); sc[qi][kk] = e; ssum += e; }
#pragma unroll
        for (int s2 = 8; s2 > 0; s2 >>= 1) ssum += __shfl_xor_sync(0xffffffffu, ssum, s2, 16);
        if (l == 0) invs[qi] = 1.f / ssum;
    }
    __syncthreads();
    if (tid < DH_) {
        float acc[QT_];
#pragma unroll
        for (int qi = 0; qi < QT_; qi++) acc[qi] = 0.f;
        for (int kk = 0; kk < nk; kk++) {
            float vv = V[base + (size_t)(kl+kk)*D_ + tid];
#pragma unroll
            for (int qi = 0; qi < QT_; qi++) acc[qi] += sc[qi][kk]*vv;
        }
#pragma unroll
        for (int qi = 0; qi < QT_; qi++)
            O[base + (size_t)(q0+qi)*D_ + tid] = acc[qi]*invs[qi];
    }
}

// ---------------- decoder: pack kernels ----------------
__device__ __forceinline__ unsigned packbf(float a, float b) {
    __nv_bfloat162 t = __float22bfloat162_rn(make_float2(a, b));
    return *(unsigned*)&t;
}

// Wh [1024][4096] -> B-fragment order: [g][q][kt][lane] uint2
__global__ void pack_whb_k(const float* __restrict__ Wh, uint2* __restrict__ out)
{
    size_t idx = (size_t)blockIdx.x*256 + threadIdx.x;
    if (idx >= (size_t)GATEB_*4*64*32) return;
    int lane = idx & 31;
    int kt = (idx >> 5) & 63;
    int q  = (idx >> 11) & 3;
    int g  = idx >> 13;
    int j  = q*1024 + g*8 + (lane >> 2);
    int k0 = kt*16 + (lane & 3)*2;
    float w0 = Wh[(size_t)k0*G4_ + j],     w1 = Wh[(size_t)(k0+1)*G4_ + j];
    float w2 = Wh[(size_t)(k0+8)*G4_ + j], w3 = Wh[(size_t)(k0+9)*G4_ + j];
    out[idx] = make_uint2(packbf(w0,w1), packbf(w2,w3));
}

// Wx [274][4096] -> [g][q][kt2 0..17][lane] uint2 (k padded to 288)
__global__ void pack_wxb_k(const float* __restrict__ Wx, uint2* __restrict__ out)
{
    size_t idx = (size_t)blockIdx.x*256 + threadIdx.x;
    if (idx >= (size_t)GATEB_*4*18*32) return;
    int lane = idx & 31;
    size_t r = idx >> 5;
    int kt = r % 18;
    int q  = (r / 18) & 3;
    int g  = r / 72;
    int j  = q*1024 + g*8 + (lane >> 2);
    int k0 = kt*16 + (lane & 3)*2;
    float w0 = (k0   < POSE_) ? Wx[(size_t)k0*G4_ + j]     : 0.f;
    float w1 = (k0+1 < POSE_) ? Wx[(size_t)(k0+1)*G4_ + j] : 0.f;
    float w2 = (k0+8 < POSE_) ? Wx[(size_t)(k0+8)*G4_ + j] : 0.f;
    float w3 = (k0+9 < POSE_) ? Wx[(size_t)(k0+9)*G4_ + j] : 0.f;
    out[idx] = make_uint2(packbf(w0,w1), packbf(w2,w3));
}

// outW[:1024] [1024][274] -> [grp 0..34][kt][lane] uint2 (n padded to 280)
__global__ void pack_owb_k(const float* __restrict__ Wo, uint2* __restrict__ out)
{
    int idx = blockIdx.x*256 + threadIdx.x;
    if (idx >= OGRP_*64*32) return;
    int lane = idx & 31;
    int kt = (idx >> 5) & 63;
    int grp = idx >> 11;
    int n  = grp*8 + (lane >> 2);
    int k0 = kt*16 + (lane & 3)*2;
    float w0=0.f, w1=0.f, w2=0.f, w3=0.f;
    if (n < POSE_) {
        w0 = Wo[(size_t)k0*POSE_ + n];     w1 = Wo[(size_t)(k0+1)*POSE_ + n];
        w2 = Wo[(size_t)(k0+8)*POSE_ + n]; w3 = Wo[(size_t)(k0+9)*POSE_ + n];
    }
    out[idx] = make_uint2(packbf(w0,w1), packbf(w2,w3));
}

// vec_h [16][1024] fp32 -> g_hb[1] bf16 padded A-layout; reset barrier counter
__global__ void init_dec_k(const float* __restrict__ vh, unsigned* __restrict__ hb)
{
    int i = blockIdx.x*256 + threadIdx.x;
    if (i == 0) g_cnt = 0;
    if (i < HBTOT_) {
        int b = i / HBW_, kw = i % HBW_;
        int k0 = kw*2;
        float v0 = (k0   < HID_) ? vh[b*HID_ + k0]   : 0.f;
        float v1 = (k0+1 < HID_) ? vh[b*HID_ + k0+1] : 0.f;
        hb[HBTOT_ + i] = packbf(v0, v1);
    }
}

__device__ __forceinline__ float sigf(float x){ return 1.f/(1.f+expf(-x)); }

__device__ __forceinline__ void mma_bf16(float* d, const unsigned* a, const unsigned* b) {
    asm volatile("mma.sync.aligned.m16n8k16.row.col.f32.bf16.bf16.f32 "
        "{%0,%1,%2,%3}, {%4,%5,%6,%7}, {%8,%9}, {%0,%1,%2,%3};"
        : "+f"(d[0]), "+f"(d[1]), "+f"(d[2]), "+f"(d[3])
        : "r"(a[0]), "r"(a[1]), "r"(a[2]), "r"(a[3]), "r"(b[0]), "r"(b[1]));
}

__device__ __forceinline__ void gsync(unsigned& phase)
{
    __threadfence();
    __syncthreads();
    if (threadIdx.x == 0) {
        atomicAdd(&g_cnt, 1u);
        phase += NB_;
        while (*((volatile unsigned*)&g_cnt) < phase) __nanosleep(64);
    }
    __syncthreads();
}

// grid = 146 x 128 threads. Blocks 0..127: gates (8 units each). 128..145: out-proj.
// dyn smem: hbs 8256 w | xbs 2368 w | red 2048 w = 50688 B
__global__ __launch_bounds__(128)
void dec_k(const uint2* __restrict__ WHB, const uint2* __restrict__ WXB,
           const uint2* __restrict__ OWB, const float* __restrict__ lb,
           const float* __restrict__ xwx, const float* __restrict__ encp,
           const float* __restrict__ vec_c, const float* __restrict__ dec0,
           unsigned* __restrict__ hb, float* __restrict__ outbuf,
           const int* __restrict__ ep)
{
    extern __shared__ unsigned smu[];
    unsigned* hbs = smu;
    unsigned* xbs = smu + HBTOT_;
    float*    red = (float*)(smu + HBTOT_ + 16*XBW_);
    float*    redo = (float*)(smu + HBTOT_);

    int tid = threadIdx.x, bx = blockIdx.x;
    int lane = tid & 31, w = tid >> 5;
    int b = lane >> 2, tg = lane & 3;
    bool isGate = bx < GATEB_;
    unsigned phase = 0;
    int p = (int)((double)(*ep) * 0.01);   // double required: fp32 100*0.01 -> 0
    int per = p + 10;

    // gate state
    int g8 = bx * 8;
    int u0 = g8 + tg*2;
    float c0=0.f, c1=0.f, c2=0.f, c3=0.f;
    if (isGate && w == 0) {
        c0 = vec_c[b*HID_ + u0];       c1 = vec_c[b*HID_ + u0 + 1];
        c2 = vec_c[(b+8)*HID_ + u0];   c3 = vec_c[(b+8)*HID_ + u0 + 1];
    }
    // out-block ids
    int ob = bx - GATEB_;
    int grp = ob*2 + (w >> 1);
    int kh = w & 1;
    bool ovalid = (grp < OGRP_);

#define HBS_COPY(hrp) { \
        const uint4* srcv = (const uint4*)(hrp); uint4* dstv = (uint4*)hbs; \
        for (int i = tid; i < HBTOT_/4; i += 128) dstv[i] = __ldcg(srcv + i); }

#define A_LOAD(buf, stride, ktv) { \
        int wA = b*(stride) + (ktv)*8 + tg; \
        a[0] = (buf)[wA]; a[1] = (buf)[wA + 8*(stride)]; \
        a[2] = (buf)[wA + 4]; a[3] = (buf)[wA + 8*(stride) + 4]; }

#define OUT_PHASE(tt, hrp) { \
        HBS_COPY(hrp); \
        __syncthreads(); \
        float d[4] = {0.f,0.f,0.f,0.f}; \
        unsigned a[4]; \
        if (ovalid) { \
            _Pragma("unroll 4") \
            for (int kt16 = 0; kt16 < 32; kt16++) { \
                int kt = kh*32 + kt16; \
                A_LOAD(hbs, HBW_, kt); \
                uint2 bb = OWB[((size_t)grp*64 + kt)*32 + lane]; \
                mma_bf16(d, a, &bb.x); \
            } \
        } \
        float* myr = redo + (w*32 + lane)*4; \
        myr[0]=d[0]; myr[1]=d[1]; myr[2]=d[2]; myr[3]=d[3]; \
        __syncthreads(); \
        if ((w & 1) == 0 && ovalid) { \
            float s0 = redo[(w*32+lane)*4+0] + redo[((w+1)*32+lane)*4+0]; \
            float s1 = redo[(w*32+lane)*4+1] + redo[((w+1)*32+lane)*4+1]; \
            float s2 = redo[(w*32+lane)*4+2] + redo[((w+1)*32+lane)*4+2]; \
            float s3 = redo[(w*32+lane)*4+3] + redo[((w+1)*32+lane)*4+3]; \
            int n0 = grp*8 + tg*2; \
            if (n0 + 1 < POSE_) { \
                size_t o0 = ((size_t)b*S_ + (tt))*POSE_ + n0; \
                size_t o1 = ((size_t)(b+8)*S_ + (tt))*POSE_ + n0; \
                float2 e0 = *(const float2*)(encp + o0); \
                float2 e1 = *(const float2*)(encp + o1); \
                *(float2*)(outbuf + o0) = make_float2(s0 + e0.x, s1 + e0.y); \
                *(float2*)(outbuf + o1) = make_float2(s2 + e1.x, s3 + e1.y); \
            } \
        } }

    for (int t = 0; t < S_; t++) {
        bool sampled = (t % per) < p;
        const unsigned* hr = hb + ((t+1)&1)*HBTOT_;
        unsigned*       hw = hb + (t&1)*HBTOT_;

        if (sampled && t > 0) {
            if (!isGate) OUT_PHASE(t-1, hr);
            gsync(phase);
        }

        if (isGate) {
            float2 xw[8];
            if (w == 0 && !sampled) {
#pragma unroll
                for (int q = 0; q < 4; q++)
#pragma unroll
                    for (int rr = 0; rr < 2; rr++)
                        xw[q*2+rr] = __ldcg((const float2*)(xwx +
                            ((size_t)(b + rr*8)*S_ + t)*G4_ + q*1024 + u0));
            }
            HBS_COPY(hr);
            if (sampled) {
                const float* xsrc0 = (t == 0) ? dec0 : (outbuf + (size_t)(t-1)*POSE_);
                // row stride between batches: dec0 is [b][POSE]; outbuf is [b][S][POSE]
                size_t bstride = (t == 0) ? (size_t)POSE_ : (size_t)S_*POSE_;
                for (int i = tid; i < 16*(XBW_-4); i += 128) {
                    int b2 = i / (XBW_-4), kw = i % (XBW_-4);
                    int k0 = kw*2;
                    const float* sp = xsrc0 + (size_t)b2*bstride;
                    float v0 = (k0   < POSE_) ? __ldcg(sp + k0)   : 0.f;
                    float v1 = (k0+1 < POSE_) ? __ldcg(sp + k0+1) : 0.f;
                    xbs[b2*XBW_ + kw] = packbf(v0, v1);
                }
            }
            __syncthreads();

            float d[4][4];
#pragma unroll
            for (int q = 0; q < 4; q++)
#pragma unroll
                for (int i = 0; i < 4; i++) d[q][i] = 0.f;
            unsigned a[4];
#pragma unroll 4
            for (int kt16 = 0; kt16 < 16; kt16++) {
                int kt = w*16 + kt16;
                A_LOAD(hbs, HBW_, kt);
#pragma unroll
                for (int q = 0; q < 4; q++) {
                    uint2 bb = WHB[(((size_t)bx*4 + q)*64 + kt)*32 + lane];
                    mma_bf16(d[q], a, &bb.x);
                }
            }
            if (sampled) {
                int e2 = min(18, w*5 + 5);
                for (int kt2 = w*5; kt2 < e2; kt2++) {
                    A_LOAD(xbs, XBW_, kt2);
#pragma unroll
                    for (int q = 0; q < 4; q++) {
                        uint2 bb = WXB[(((size_t)bx*4 + q)*18 + kt2)*32 + lane];
                        mma_bf16(d[q], a, &bb.x);
                    }
                }
            }
            {
                float* myr = red + (w*32 + lane)*16;
#pragma unroll
                for (int q = 0; q < 4; q++)
#pragma unroll
                    for (int i = 0; i < 4; i++) myr[q*4+i] = d[q][i];
            }
            __syncthreads();

            if (w == 0) {
                float s[16];
#pragma unroll
                for (int i = 0; i < 16; i++) s[i] = 0.f;
#pragma unroll
                for (int w2 = 0; w2 < 4; w2++) {
                    const float4* r4 = (const float4*)(red + (w2*32 + lane)*16);
#pragma unroll
                    for (int q = 0; q < 4; q++) {
                        float4 v = r4[q];
                        s[q*4+0] += v.x; s[q*4+1] += v.y; s[q*4+2] += v.z; s[q*4+3] += v.w;
                    }
                }
                float gate[4][4];
#pragma unroll
                for (int q = 0; q < 4; q++) {
                    float2 lbv = *(const float2*)(lb + q*1024 + u0);
                    gate[q][0] = s[q*4+0] + lbv.x;
                    gate[q][1] = s[q*4+1] + lbv.y;
                    gate[q][2] = s[q*4+2] + lbv.x;
                    gate[q][3] = s[q*4+3] + lbv.y;
                    if (!sampled) {
                        gate[q][0] += xw[q*2].x;   gate[q][1] += xw[q*2].y;
                        gate[q][2] += xw[q*2+1].x; gate[q][3] += xw[q*2+1].y;
                    }
                }
                float cc[4] = {c0, c1, c2, c3};
                float hh[4];
#pragma unroll
                for (int e = 0; e < 4; e++) {
                    float cv = sigf(gate[1][e])*cc[e] + sigf(gate[0][e])*tanhf(gate[2][e]);
                    hh[e] = sigf(gate[3][e])*tanhf(cv);
                    cc[e] = cv;
                }
                c0 = cc[0]; c1 = cc[1]; c2 = cc[2]; c3 = cc[3];
                hw[b*HBW_ + bx*4 + tg]     = packbf(hh[0], hh[1]);
                hw[(b+8)*HBW_ + bx*4 + tg] = packbf(hh[2], hh[3]);
            }
        } else {
            if (t > 0 && !sampled) OUT_PHASE(t-1, hr);
        }
        gsync(phase);
    }
    if (!isGate) {
        const unsigned* hlast = hb + ((S_-1)&1)*HBTOT_;
        OUT_PHASE(S_-1, hlast);
    }
#undef OUT_PHASE
#undef A_LOAD
#undef HBS_COPY
}

extern "C" void kernel_launch(void* const* d_in, const int* in_sizes, int n_in,
                              void* d_out, int out_size)
{
    (void)in_sizes; (void)n_in; (void)out_size;
    const float* src_seq = (const float*)d_in[0];
    const int*   src_pos = (const int*)  d_in[1];
    const float* tgt_seq = (const float*)d_in[2];
    const float* vec_h   = (const float*)d_in[3];
    const float* vec_c   = (const float*)d_in[4];
    const float* dec0    = (const float*)d_in[5];
    const float* emb_W   = (const float*)d_in[6];
    const float* emb_b   = (const float*)d_in[7];
    const float* pos_t   = (const float*)d_in[8];
    const float* Wq      = (const float*)d_in[9];
    const float* Wk      = (const float*)d_in[10];
    const float* Wv      = (const float*)d_in[11];
    const float* Wo      = (const float*)d_in[12];
    const float* ln1g    = (const float*)d_in[13];
    const float* ln1b    = (const float*)d_in[14];
    const float* fW1     = (const float*)d_in[15];
    const float* fb1     = (const float*)d_in[16];
    const float* fW2     = (const float*)d_in[17];
    const float* fb2     = (const float*)d_in[18];
    const float* ln2g    = (const float*)d_in[19];
    const float* ln2b    = (const float*)d_in[20];
    const float* lWx     = (const float*)d_in[21];
    const float* lWh     = (const float*)d_in[22];
    const float* lb      = (const float*)d_in[23];
    const float* outW    = (const float*)d_in[24];
    const float* outb    = (const float*)d_in[25];
    const int*   ep      = (const int*)  d_in[26];
    float* out = (float*)d_out;

    void *px,*pq,*pk,*pv,*po,*pr1,*px2,*ph1,*pt2,*penc,*pxwx,*pencp,*phb,*pwhb,*pwxb,*powb;
    cudaGetSymbolAddress(&px,  g_x);   cudaGetSymbolAddress(&pq,  g_q);
    cudaGetSymbolAddress(&pk,  g_k);   cudaGetSymbolAddress(&pv,  g_v);
    cudaGetSymbolAddress(&po,  g_o);   cudaGetSymbolAddress(&pr1, g_r1);
    cudaGetSymbolAddress(&px2, g_x2);  cudaGetSymbolAddress(&ph1, g_h1);
    cudaGetSymbolAddress(&pt2, g_t2);  cudaGetSymbolAddress(&penc,g_enc);
    cudaGetSymbolAddress(&pxwx,g_xwx); cudaGetSymbolAddress(&pencp,g_encp);
    cudaGetSymbolAddress(&phb, g_hb);  cudaGetSymbolAddress(&pwhb,g_whb);
    cudaGetSymbolAddress(&pwxb,g_wxb); cudaGetSymbolAddress(&powb,g_owb);
    float *X=(float*)px, *Qb=(float*)pq, *Kb=(float*)pk, *Vb=(float*)pv, *Ob=(float*)po;
    float *R1=(float*)pr1, *X2=(float*)px2, *H1=(float*)ph1, *T2=(float*)pt2, *ENC=(float*)penc;
    float *XWX=(float*)pxwx, *ENCP=(float*)pencp;
    unsigned *HB=(unsigned*)phb;
    uint2 *WHB=(uint2*)pwhb, *WXB=(uint2*)pwxb, *OWB=(uint2*)powb;

    cudaFuncSetAttribute(attn_k, cudaFuncAttributeMaxDynamicSharedMemorySize, KSPAN_*KROW_*4);
    cudaFuncSetAttribute(dec_k,  cudaFuncAttributeMaxDynamicSharedMemorySize, 50688);

    dim3 gD((D_+127)/128, M_/128), gF((FFN_+127)/128, M_/128);
    dim3 gG4((G4_+127)/128, M_/128), gP((POSE_+127)/128, M_/128);

    // encoder
    gemm_k<EPI_POS><<<gD,256>>>(src_seq, emb_W, X, M_, D_, FRAME_, emb_b, nullptr, pos_t, src_pos);
    gemm_k<EPI_NONE><<<gD,256>>>(X, Wq, Qb, M_, D_, D_, nullptr, nullptr, nullptr, nullptr);
    gemm_k<EPI_NONE><<<gD,256>>>(X, Wk, Kb, M_, D_, D_, nullptr, nullptr, nullptr, nullptr);
    gemm_k<EPI_NONE><<<gD,256>>>(X, Wv, Vb, M_, D_, D_, nullptr, nullptr, nullptr, nullptr);
    attn_k<<<dim3(S_/QT_, H_, B_),128,KSPAN_*KROW_*4>>>(Qb, Kb, Vb, Ob);
    gemm_k<EPI_ADD><<<gD,256>>>(Ob, Wo, R1, M_, D_, D_, nullptr, X, nullptr, nullptr);
    ln_k<<<M_,256>>>(R1, X2, ln1g, ln1b);
    gemm_k<EPI_BIAS_RELU><<<gF,256>>>(X2, fW1, H1, M_, FFN_, D_, fb1, nullptr, nullptr, nullptr);
    gemm_k<EPI_BIAS_ADD><<<gD,256>>>(H1, fW2, T2, M_, D_, FFN_, fb2, X2, nullptr, nullptr);
    ln_k<<<M_,256>>>(T2, ENC, ln2g, ln2b);

    // decoder precompute
    gemm_k<EPI_NONE><<<gG4,256>>>(tgt_seq, lWx, XWX, M_, G4_, POSE_, nullptr, nullptr, nullptr, nullptr);
    gemm_k<EPI_BIAS><<<gP,256>>>(ENC, outW + (size_t)HID_*POSE_, ENCP, M_, POSE_, D_, outb, nullptr, nullptr, nullptr);
    pack_whb_k<<<(GATEB_*4*64*32+255)/256,256>>>(lWh, WHB);
    pack_wxb_k<<<(GATEB_*4*18*32+255)/256,256>>>(lWx, WXB);
    pack_owb_k<<<(OGRP_*64*32+255)/256,256>>>(outW, OWB);
    init_dec_k<<<(HBTOT_+255)/256,256>>>(vec_h, HB);

    dec_k<<<NB_,128,50688>>>(WHB, WXB, OWB, lb, XWX, ENCP, vec_c, dec0, HB, out, ep);
}

// round 7
// speedup vs baseline: 1.3066x; 1.2731x over previous
#include <cuda_runtime.h>
#include <cuda_bf16.h>
#include <math.h>

#define B_ 16
#define S_ 512
#define FRAME_ 438
#define D_ 800
#define H_ 8
#define DH_ 100
#define FFN_ 1024
#define HID_ 1024
#define POSE_ 274
#define WIN_ 100
#define M_ (B_*S_)
#define G4_ (4*HID_)
#define QT_ 8
#define KSPAN_ (2*WIN_+QT_)
#define KROW_ 101
#define GATEB_ 128
#define OUTB_ 18
#define NB_ (GATEB_+OUTB_)
#define HBW_ 516          // words per h row (1032 halves: 1024 + 8 pad)
#define HBTOT_ (16*HBW_)  // 8256 words per h buffer
#define XBW_ 148          // words per x row (296 halves: 288 + 8 pad)
#define OGRP_ 35          // ceil(274/8)

__device__ float g_x[M_*D_];
__device__ float g_q[M_*D_];
__device__ float g_k[M_*D_];
__device__ float g_v[M_*D_];
__device__ float g_o[M_*D_];
__device__ float g_r1[M_*D_];
__device__ float g_x2[M_*D_];
__device__ float g_h1[M_*FFN_];
__device__ float g_t2[M_*D_];
__device__ float g_enc[M_*D_];
__device__ float g_xwx[(size_t)M_*G4_];
__device__ float g_encp[M_*POSE_];
__device__ __align__(16) unsigned g_hb[4*HBTOT_];   // 4-deep h ring
__device__ uint2 g_whb[(size_t)GATEB_*4*64*32];
__device__ uint2 g_wxb[(size_t)GATEB_*4*18*32];
__device__ uint2 g_owb[(size_t)OGRP_*64*32];
__device__ unsigned g_cnt;    // h production counter (+1 per gate block per step)
__device__ unsigned g_ocnt;   // out production counter (+1 per out block per phase)

enum { EPI_NONE=0, EPI_POS=1, EPI_ADD=2, EPI_BIAS_RELU=3, EPI_BIAS_ADD=4, EPI_BIAS=5 };

template<int EPI>
__global__ __launch_bounds__(256)
void gemm_k(const float* __restrict__ A, const float* __restrict__ W,
            float* __restrict__ C, int Mm, int Nn, int Kk,
            const float* __restrict__ bias, const float* __restrict__ addend,
            const float* __restrict__ pos_table, const int* __restrict__ pos_idx)
{
    __shared__ float As[16][132];
    __shared__ float Ws[16][128];
    int tid = threadIdx.x, tx = tid & 15, ty = tid >> 4;
    int rowBase = blockIdx.y * 128, colBase = blockIdx.x * 128;
    float acc[8][8];
#pragma unroll
    for (int i = 0; i < 8; i++)
#pragma unroll
        for (int j = 0; j < 8; j++) acc[i][j] = 0.f;

    for (int k0 = 0; k0 < Kk; k0 += 16) {
#pragma unroll
        for (int i = 0; i < 8; i++) {
            int idx = i*256 + tid, r = idx >> 4, c = idx & 15, gk = k0 + c;
            As[c][r] = (gk < Kk) ? A[(size_t)(rowBase+r)*Kk + gk] : 0.f;
        }
#pragma unroll
        for (int i = 0; i < 8; i++) {
            int idx = i*256 + tid, kk = idx >> 7, n = idx & 127;
            int gk = k0 + kk, gn = colBase + n;
            Ws[kk][n] = (gk < Kk && gn < Nn) ? W[(size_t)gk*Nn + gn] : 0.f;
        }
        __syncthreads();
#pragma unroll
        for (int kk = 0; kk < 16; kk++) {
            float4 a0 = *(const float4*)&As[kk][ty*4];
            float4 a1 = *(const float4*)&As[kk][64 + ty*4];
            float4 w0 = *(const float4*)&Ws[kk][tx*4];
            float4 w1 = *(const float4*)&Ws[kk][64 + tx*4];
            float a[8] = {a0.x,a0.y,a0.z,a0.w,a1.x,a1.y,a1.z,a1.w};
            float w[8] = {w0.x,w0.y,w0.z,w0.w,w1.x,w1.y,w1.z,w1.w};
#pragma unroll
            for (int i = 0; i < 8; i++)
#pragma unroll
                for (int j = 0; j < 8; j++) acc[i][j] += a[i]*w[j];
        }
        __syncthreads();
    }
#pragma unroll
    for (int i = 0; i < 8; i++) {
        int m = rowBase + ((i < 4) ? (ty*4 + i) : (64 + ty*4 + i - 4));
#pragma unroll
        for (int j = 0; j < 8; j++) {
            int n = colBase + ((j < 4) ? (tx*4 + j) : (64 + tx*4 + j - 4));
            if (n < Nn) {
                float v = acc[i][j];
                if (EPI == EPI_POS)            v += bias[n] + pos_table[(size_t)pos_idx[m]*Nn + n];
                else if (EPI == EPI_ADD)       v += addend[(size_t)m*Nn + n];
                else if (EPI == EPI_BIAS_RELU) { v += bias[n]; v = v > 0.f ? v : 0.f; }
                else if (EPI == EPI_BIAS_ADD)  v += bias[n] + addend[(size_t)m*Nn + n];
                else if (EPI == EPI_BIAS)      v += bias[n];
                C[(size_t)m*Nn + n] = v;
            }
        }
    }
}

__global__ __launch_bounds__(256)
void ln_k(const float* __restrict__ in, float* __restrict__ out,
          const float* __restrict__ g, const float* __restrict__ b)
{
    __shared__ float buf[D_];
    __shared__ float red[256];
    int row = blockIdx.x, tid = threadIdx.x;
    float s = 0.f;
    for (int i = tid; i < D_; i += 256) { float v = in[(size_t)row*D_ + i]; buf[i] = v; s += v; }
    red[tid] = s; __syncthreads();
    for (int st = 128; st > 0; st >>= 1) { if (tid < st) red[tid] += red[tid+st]; __syncthreads(); }
    float mean = red[0] / (float)D_;
    __syncthreads();
    float ss = 0.f;
    for (int i = tid; i < D_; i += 256) { float d = buf[i]-mean; ss += d*d; }
    red[tid] = ss; __syncthreads();
    for (int st = 128; st > 0; st >>= 1) { if (tid < st) red[tid] += red[tid+st]; __syncthreads(); }
    float inv = rsqrtf(red[0]/(float)D_ + 1e-6f);
    for (int i = tid; i < D_; i += 256)
        out[(size_t)row*D_ + i] = (buf[i]-mean)*inv*g[i] + b[i];
}

__global__ __launch_bounds__(128)
void attn_k(const float* __restrict__ Q, const float* __restrict__ K,
            const float* __restrict__ V, float* __restrict__ O)
{
    extern __shared__ float ks[];
    __shared__ float qs[QT_*DH_];
    __shared__ float sc[QT_][KSPAN_];
    __shared__ float invs[QT_];
    int tid = threadIdx.x;
    int q0 = blockIdx.x * QT_, h = blockIdx.y, b = blockIdx.z;
    int kl = max(0, q0 - WIN_);
    int kh = min(S_-1, q0 + QT_-1 + WIN_);
    int nk = kh - kl + 1;
    size_t base = ((size_t)b*S_)*D_ + (size_t)h*DH_;

    for (int idx = tid; idx < QT_*DH_; idx += 128) {
        int qi = idx / DH_, dd = idx % DH_;
        qs[idx] = Q[base + (size_t)(q0+qi)*D_ + dd];
    }
    for (int idx = tid; idx < nk*DH_; idx += 128) {
        int kk = idx / DH_, dd = idx % DH_;
        ks[kk*KROW_ + dd] = K[base + (size_t)(kl+kk)*D_ + dd];
    }
    __syncthreads();

    for (int pid = tid; pid < QT_*nk; pid += 128) {
        int kk = pid % nk, qi = pid / nk;
        int qq = q0 + qi, kp = kl + kk;
        float v;
        if (kp >= qq - WIN_ && kp <= qq + WIN_) {
            float d = 0.f;
            for (int i = 0; i < DH_; i++) d += qs[qi*DH_ + i]*ks[kk*KROW_ + i];
            v = d * 0.1f;
        } else v = -1e30f;
        sc[qi][kk] = v;
    }
    __syncthreads();
    {
        int qi = tid >> 4, l = tid & 15;
        float m = -1e30f;
        for (int kk = l; kk < nk; kk += 16) m = fmaxf(m, sc[qi][kk]);
#pragma unroll
        for (int s2 = 8; s2 > 0; s2 >>= 1) m = fmaxf(m, __shfl_xor_sync(0xffffffffu, m, s2, 16));
        float ssum = 0.f;
        for (int kk = l; kk < nk; kk += 16) { float e = expf(sc[qi][kk]-m); sc[qi][kk] = e; ssum += e; }
#pragma unroll
        for (int s2 = 8; s2 > 0; s2 >>= 1) ssum += __shfl_xor_sync(0xffffffffu, ssum, s2, 16);
        if (l == 0) invs[qi] = 1.f / ssum;
    }
    __syncthreads();
    if (tid < DH_) {
        float acc[QT_];
#pragma unroll
        for (int qi = 0; qi < QT_; qi++) acc[qi] = 0.f;
        for (int kk = 0; kk < nk; kk++) {
            float vv = V[base + (size_t)(kl+kk)*D_ + tid];
#pragma unroll
            for (int qi = 0; qi < QT_; qi++) acc[qi] += sc[qi][kk]*vv;
        }
#pragma unroll
        for (int qi = 0; qi < QT_; qi++)
            O[base + (size_t)(q0+qi)*D_ + tid] = acc[qi]*invs[qi];
    }
}

// ---------------- decoder: pack kernels ----------------
__device__ __forceinline__ unsigned packbf(float a, float b) {
    __nv_bfloat162 t = __float22bfloat162_rn(make_float2(a, b));
    return *(unsigned*)&t;
}

__global__ void pack_whb_k(const float* __restrict__ Wh, uint2* __restrict__ out)
{
    size_t idx = (size_t)blockIdx.x*256 + threadIdx.x;
    if (idx >= (size_t)GATEB_*4*64*32) return;
    int lane = idx & 31;
    int kt = (idx >> 5) & 63;
    int q  = (idx >> 11) & 3;
    int g  = idx >> 13;
    int j  = q*1024 + g*8 + (lane >> 2);
    int k0 = kt*16 + (lane & 3)*2;
    float w0 = Wh[(size_t)k0*G4_ + j],     w1 = Wh[(size_t)(k0+1)*G4_ + j];
    float w2 = Wh[(size_t)(k0+8)*G4_ + j], w3 = Wh[(size_t)(k0+9)*G4_ + j];
    out[idx] = make_uint2(packbf(w0,w1), packbf(w2,w3));
}

__global__ void pack_wxb_k(const float* __restrict__ Wx, uint2* __restrict__ out)
{
    size_t idx = (size_t)blockIdx.x*256 + threadIdx.x;
    if (idx >= (size_t)GATEB_*4*18*32) return;
    int lane = idx & 31;
    size_t r = idx >> 5;
    int kt = r % 18;
    int q  = (r / 18) & 3;
    int g  = r / 72;
    int j  = q*1024 + g*8 + (lane >> 2);
    int k0 = kt*16 + (lane & 3)*2;
    float w0 = (k0   < POSE_) ? Wx[(size_t)k0*G4_ + j]     : 0.f;
    float w1 = (k0+1 < POSE_) ? Wx[(size_t)(k0+1)*G4_ + j] : 0.f;
    float w2 = (k0+8 < POSE_) ? Wx[(size_t)(k0+8)*G4_ + j] : 0.f;
    float w3 = (k0+9 < POSE_) ? Wx[(size_t)(k0+9)*G4_ + j] : 0.f;
    out[idx] = make_uint2(packbf(w0,w1), packbf(w2,w3));
}

__global__ void pack_owb_k(const float* __restrict__ Wo, uint2* __restrict__ out)
{
    int idx = blockIdx.x*256 + threadIdx.x;
    if (idx >= OGRP_*64*32) return;
    int lane = idx & 31;
    int kt = (idx >> 5) & 63;
    int grp = idx >> 11;
    int n  = grp*8 + (lane >> 2);
    int k0 = kt*16 + (lane & 3)*2;
    float w0=0.f, w1=0.f, w2=0.f, w3=0.f;
    if (n < POSE_) {
        w0 = Wo[(size_t)k0*POSE_ + n];     w1 = Wo[(size_t)(k0+1)*POSE_ + n];
        w2 = Wo[(size_t)(k0+8)*POSE_ + n]; w3 = Wo[(size_t)(k0+9)*POSE_ + n];
    }
    out[idx] = make_uint2(packbf(w0,w1), packbf(w2,w3));
}

// vec_h -> h ring slot 3 (h_{-1}); reset counters
__global__ void init_dec_k(const float* __restrict__ vh, unsigned* __restrict__ hb)
{
    int i = blockIdx.x*256 + threadIdx.x;
    if (i == 0) { g_cnt = 0; g_ocnt = 0; }
    if (i < HBTOT_) {
        int b = i / HBW_, kw = i % HBW_;
        int k0 = kw*2;
        float v0 = (k0   < HID_) ? vh[b*HID_ + k0]   : 0.f;
        float v1 = (k0+1 < HID_) ? vh[b*HID_ + k0+1] : 0.f;
        hb[3*HBTOT_ + i] = packbf(v0, v1);
    }
}

__device__ __forceinline__ float sigf(float x){ return 1.f/(1.f+expf(-x)); }

__device__ __forceinline__ void mma_bf16(float* d, const unsigned* a, const unsigned* b) {
    asm volatile("mma.sync.aligned.m16n8k16.row.col.f32.bf16.bf16.f32 "
        "{%0,%1,%2,%3}, {%4,%5,%6,%7}, {%8,%9}, {%0,%1,%2,%3};"
        : "+f"(d[0]), "+f"(d[1]), "+f"(d[2]), "+f"(d[3])
        : "r"(a[0]), "r"(a[1]), "r"(a[2]), "r"(a[3]), "r"(b[0]), "r"(b[1]));
}

__device__ __forceinline__ unsigned ld_acq(const unsigned* p) {
    unsigned v;
    asm volatile("ld.acquire.gpu.global.u32 %0, [%1];" : "=r"(v) : "l"(p) : "memory");
    return v;
}
__device__ __forceinline__ void red_rel(unsigned* p) {
    asm volatile("red.release.gpu.global.add.u32 [%0], 1;" :: "l"(p) : "memory");
}

// grid = 146 x 128 threads. Blocks 0..127: gates (8 units each). 128..145: out-proj.
// dyn smem: hbs 8256 w | xbs 2368 w | red 2048 w = 50688 B
__global__ __launch_bounds__(128)
void dec_k(const uint2* __restrict__ WHB, const uint2* __restrict__ WXB,
           const uint2* __restrict__ OWB, const float* __restrict__ lb,
           const float* __restrict__ xwx, const float* __restrict__ encp,
           const float* __restrict__ vec_c, const float* __restrict__ dec0,
           unsigned* __restrict__ hb, float* __restrict__ outbuf,
           const int* __restrict__ ep)
{
    extern __shared__ unsigned smu[];
    unsigned* hbs = smu;
    unsigned* xbs = smu + HBTOT_;
    float*    red = (float*)(smu + HBTOT_ + 16*XBW_);
    float*    redo = (float*)(smu + HBTOT_);

    int tid = threadIdx.x, bx = blockIdx.x;
    int lane = tid & 31, w = tid >> 5;
    int b = lane >> 2, tg = lane & 3;
    bool isGate = bx < GATEB_;
    int p = (int)((double)(*ep) * 0.01);   // double required: fp32 100*0.01 -> 0
    int per = p + 10;

    int g8 = bx * 8;
    int u0 = g8 + tg*2;
    float c0=0.f, c1=0.f, c2=0.f, c3=0.f;
    if (isGate && w == 0) {
        c0 = vec_c[b*HID_ + u0];       c1 = vec_c[b*HID_ + u0 + 1];
        c2 = vec_c[(b+8)*HID_ + u0];   c3 = vec_c[(b+8)*HID_ + u0 + 1];
    }
    int ob = bx - GATEB_;
    int grp = ob*2 + (w >> 1);
    int kh = w & 1;
    bool ovalid = (grp < OGRP_);

#define HBS_COPY(hrp) { \
        const uint4* srcv = (const uint4*)(hrp); uint4* dstv = (uint4*)hbs; \
        for (int i = tid; i < HBTOT_/4; i += 128) dstv[i] = __ldcg(srcv + i); }

#define A_LOAD(buf, stride, ktv) { \
        int wA = b*(stride) + (ktv)*8 + tg; \
        a[0] = (buf)[wA]; a[1] = (buf)[wA + 8*(stride)]; \
        a[2] = (buf)[wA + 4]; a[3] = (buf)[wA + 8*(stride) + 4]; }

    if (isGate) {
        for (int t = 0; t < S_; t++) {
            bool sampled = (t % per) < p;
            const unsigned* hr = hb + ((t+3)&3)*(size_t)HBTOT_;
            unsigned*       hw = hb + (t&3)*(size_t)HBTOT_;

            // waits: h_{t-1} produced; out caught up (sampled or ring protection)
            unsigned needO = 0;
            if (sampled) needO = 18u*(unsigned)t;
            else if (t >= 4) needO = 18u*(unsigned)(t-3);
            if (tid == 0) {
                if (t > 0) { unsigned needH = 128u*(unsigned)t;
                    while (ld_acq(&g_cnt) < needH) ; }
                if (needO)  while (ld_acq(&g_ocnt) < needO) ;
            }
            __syncthreads();

            float2 xw[8];
            if (w == 0 && !sampled) {
#pragma unroll
                for (int q = 0; q < 4; q++)
#pragma unroll
                    for (int rr = 0; rr < 2; rr++)
                        xw[q*2+rr] = __ldcg((const float2*)(xwx +
                            ((size_t)(b + rr*8)*S_ + t)*G4_ + q*1024 + u0));
            }
            HBS_COPY(hr);
            if (sampled) {
                const float* xsrc0 = (t == 0) ? dec0 : (outbuf + (size_t)(t-1)*POSE_);
                size_t bstride = (t == 0) ? (size_t)POSE_ : (size_t)S_*POSE_;
                for (int i = tid; i < 16*(XBW_-4); i += 128) {
                    int b2 = i / (XBW_-4), kw = i % (XBW_-4);
                    int k0 = kw*2;
                    const float* sp = xsrc0 + (size_t)b2*bstride;
                    float v0 = (k0   < POSE_) ? __ldcg(sp + k0)   : 0.f;
                    float v1 = (k0+1 < POSE_) ? __ldcg(sp + k0+1) : 0.f;
                    xbs[b2*XBW_ + kw] = packbf(v0, v1);
                }
            }
            __syncthreads();

            float d[4][4];
#pragma unroll
            for (int q = 0; q < 4; q++)
#pragma unroll
                for (int i = 0; i < 4; i++) d[q][i] = 0.f;
            unsigned a[4];
#pragma unroll 4
            for (int kt16 = 0; kt16 < 16; kt16++) {
                int kt = w*16 + kt16;
                A_LOAD(hbs, HBW_, kt);
#pragma unroll
                for (int q = 0; q < 4; q++) {
                    uint2 bb = WHB[(((size_t)bx*4 + q)*64 + kt)*32 + lane];
                    mma_bf16(d[q], a, &bb.x);
                }
            }
            if (sampled) {
                int e2 = min(18, w*5 + 5);
                for (int kt2 = w*5; kt2 < e2; kt2++) {
                    A_LOAD(xbs, XBW_, kt2);
#pragma unroll
                    for (int q = 0; q < 4; q++) {
                        uint2 bb = WXB[(((size_t)bx*4 + q)*18 + kt2)*32 + lane];
                        mma_bf16(d[q], a, &bb.x);
                    }
                }
            }
            {
                float* myr = red + (w*32 + lane)*16;
#pragma unroll
                for (int q = 0; q < 4; q++)
#pragma unroll
                    for (int i = 0; i < 4; i++) myr[q*4+i] = d[q][i];
            }
            __syncthreads();

            if (w == 0) {
                float s[16];
#pragma unroll
                for (int i = 0; i < 16; i++) s[i] = 0.f;
#pragma unroll
                for (int w2 = 0; w2 < 4; w2++) {
                    const float4* r4 = (const float4*)(red + (w2*32 + lane)*16);
#pragma unroll
                    for (int q = 0; q < 4; q++) {
                        float4 v = r4[q];
                        s[q*4+0] += v.x; s[q*4+1] += v.y; s[q*4+2] += v.z; s[q*4+3] += v.w;
                    }
                }
                float gate[4][4];
#pragma unroll
                for (int q = 0; q < 4; q++) {
                    float2 lbv = *(const float2*)(lb + q*1024 + u0);
                    gate[q][0] = s[q*4+0] + lbv.x;
                    gate[q][1] = s[q*4+1] + lbv.y;
                    gate[q][2] = s[q*4+2] + lbv.x;
                    gate[q][3] = s[q*4+3] + lbv.y;
                    if (!sampled) {
                        gate[q][0] += xw[q*2].x;   gate[q][1] += xw[q*2].y;
                        gate[q][2] += xw[q*2+1].x; gate[q][3] += xw[q*2+1].y;
                    }
                }
                float cc[4] = {c0, c1, c2, c3};
                float hh[4];
#pragma unroll
                for (int e = 0; e < 4; e++) {
                    float cv = sigf(gate[1][e])*cc[e] + sigf(gate[0][e])*tanhf(gate[2][e]);
                    hh[e] = sigf(gate[3][e])*tanhf(cv);
                    cc[e] = cv;
                }
                c0 = cc[0]; c1 = cc[1]; c2 = cc[2]; c3 = cc[3];
                hw[b*HBW_ + bx*4 + tg]     = packbf(hh[0], hh[1]);
                hw[(b+8)*HBW_ + bx*4 + tg] = packbf(hh[2], hh[3]);
            }
            __syncthreads();
            if (tid == 0) red_rel(&g_cnt);
        }
    } else {
        for (int t = 0; t < S_; t++) {
            if (tid == 0) {
                unsigned needH = 128u*(unsigned)(t+1);
                while (ld_acq(&g_cnt) < needH) ;
            }
            __syncthreads();
            const unsigned* hrp = hb + (t&3)*(size_t)HBTOT_;
            HBS_COPY(hrp);
            __syncthreads();
            float d[4] = {0.f,0.f,0.f,0.f};
            unsigned a[4];
            if (ovalid) {
#pragma unroll 4
                for (int kt16 = 0; kt16 < 32; kt16++) {
                    int kt = kh*32 + kt16;
                    A_LOAD(hbs, HBW_, kt);
                    uint2 bb = OWB[((size_t)grp*64 + kt)*32 + lane];
                    mma_bf16(d, a, &bb.x);
                }
            }
            float* myr = redo + (w*32 + lane)*4;
            myr[0]=d[0]; myr[1]=d[1]; myr[2]=d[2]; myr[3]=d[3];
            __syncthreads();
            if ((w & 1) == 0 && ovalid) {
                float s0 = redo[(w*32+lane)*4+0] + redo[((w+1)*32+lane)*4+0];
                float s1 = redo[(w*32+lane)*4+1] + redo[((w+1)*32+lane)*4+1];
                float s2 = redo[(w*32+lane)*4+2] + redo[((w+1)*32+lane)*4+2];
                float s3 = redo[(w*32+lane)*4+3] + redo[((w+1)*32+lane)*4+3];
                int n0 = grp*8 + tg*2;
                if (n0 + 1 < POSE_) {
                    size_t o0 = ((size_t)b*S_ + t)*POSE_ + n0;
                    size_t o1 = ((size_t)(b+8)*S_ + t)*POSE_ + n0;
                    float2 e0 = *(const float2*)(encp + o0);
                    float2 e1 = *(const float2*)(encp + o1);
                    *(float2*)(outbuf + o0) = make_float2(s0 + e0.x, s1 + e0.y);
                    *(float2*)(outbuf + o1) = make_float2(s2 + e1.x, s3 + e1.y);
                }
            }
            __syncthreads();
            if (tid == 0) red_rel(&g_ocnt);
        }
    }
#undef A_LOAD
#undef HBS_COPY
}

extern "C" void kernel_launch(void* const* d_in, const int* in_sizes, int n_in,
                              void* d_out, int out_size)
{
    (void)in_sizes; (void)n_in; (void)out_size;
    const float* src_seq = (const float*)d_in[0];
    const int*   src_pos = (const int*)  d_in[1];
    const float* tgt_seq = (const float*)d_in[2];
    const float* vec_h   = (const float*)d_in[3];
    const float* vec_c   = (const float*)d_in[4];
    const float* dec0    = (const float*)d_in[5];
    const float* emb_W   = (const float*)d_in[6];
    const float* emb_b   = (const float*)d_in[7];
    const float* pos_t   = (const float*)d_in[8];
    const float* Wq      = (const float*)d_in[9];
    const float* Wk      = (const float*)d_in[10];
    const float* Wv      = (const float*)d_in[11];
    const float* Wo      = (const float*)d_in[12];
    const float* ln1g    = (const float*)d_in[13];
    const float* ln1b    = (const float*)d_in[14];
    const float* fW1     = (const float*)d_in[15];
    const float* fb1     = (const float*)d_in[16];
    const float* fW2     = (const float*)d_in[17];
    const float* fb2     = (const float*)d_in[18];
    const float* ln2g    = (const float*)d_in[19];
    const float* ln2b    = (const float*)d_in[20];
    const float* lWx     = (const float*)d_in[21];
    const float* lWh     = (const float*)d_in[22];
    const float* lb      = (const float*)d_in[23];
    const float* outW    = (const float*)d_in[24];
    const float* outb    = (const float*)d_in[25];
    const int*   ep      = (const int*)  d_in[26];
    float* out = (float*)d_out;

    void *px,*pq,*pk,*pv,*po,*pr1,*px2,*ph1,*pt2,*penc,*pxwx,*pencp,*phb,*pwhb,*pwxb,*powb;
    cudaGetSymbolAddress(&px,  g_x);   cudaGetSymbolAddress(&pq,  g_q);
    cudaGetSymbolAddress(&pk,  g_k);   cudaGetSymbolAddress(&pv,  g_v);
    cudaGetSymbolAddress(&po,  g_o);   cudaGetSymbolAddress(&pr1, g_r1);
    cudaGetSymbolAddress(&px2, g_x2);  cudaGetSymbolAddress(&ph1, g_h1);
    cudaGetSymbolAddress(&pt2, g_t2);  cudaGetSymbolAddress(&penc,g_enc);
    cudaGetSymbolAddress(&pxwx,g_xwx); cudaGetSymbolAddress(&pencp,g_encp);
    cudaGetSymbolAddress(&phb, g_hb);  cudaGetSymbolAddress(&pwhb,g_whb);
    cudaGetSymbolAddress(&pwxb,g_wxb); cudaGetSymbolAddress(&powb,g_owb);
    float *X=(float*)px, *Qb=(float*)pq, *Kb=(float*)pk, *Vb=(float*)pv, *Ob=(float*)po;
    float *R1=(float*)pr1, *X2=(float*)px2, *H1=(float*)ph1, *T2=(float*)pt2, *ENC=(float*)penc;
    float *XWX=(float*)pxwx, *ENCP=(float*)pencp;
    unsigned *HB=(unsigned*)phb;
    uint2 *WHB=(uint2*)pwhb, *WXB=(uint2*)pwxb, *OWB=(uint2*)powb;

    cudaFuncSetAttribute(attn_k, cudaFuncAttributeMaxDynamicSharedMemorySize, KSPAN_*KROW_*4);
    cudaFuncSetAttribute(dec_k,  cudaFuncAttributeMaxDynamicSharedMemorySize, 50688);

    dim3 gD((D_+127)/128, M_/128), gF((FFN_+127)/128, M_/128);
    dim3 gG4((G4_+127)/128, M_/128), gP((POSE_+127)/128, M_/128);

    // encoder
    gemm_k<EPI_POS><<<gD,256>>>(src_seq, emb_W, X, M_, D_, FRAME_, emb_b, nullptr, pos_t, src_pos);
    gemm_k<EPI_NONE><<<gD,256>>>(X, Wq, Qb, M_, D_, D_, nullptr, nullptr, nullptr, nullptr);
    gemm_k<EPI_NONE><<<gD,256>>>(X, Wk, Kb, M_, D_, D_, nullptr, nullptr, nullptr, nullptr);
    gemm_k<EPI_NONE><<<gD,256>>>(X, Wv, Vb, M_, D_, D_, nullptr, nullptr, nullptr, nullptr);
    attn_k<<<dim3(S_/QT_, H_, B_),128,KSPAN_*KROW_*4>>>(Qb, Kb, Vb, Ob);
    gemm_k<EPI_ADD><<<gD,256>>>(Ob, Wo, R1, M_, D_, D_, nullptr, X, nullptr, nullptr);
    ln_k<<<M_,256>>>(R1, X2, ln1g, ln1b);
    gemm_k<EPI_BIAS_RELU><<<gF,256>>>(X2, fW1, H1, M_, FFN_, D_, fb1, nullptr, nullptr, nullptr);
    gemm_k<EPI_BIAS_ADD><<<gD,256>>>(H1, fW2, T2, M_, D_, FFN_, fb2, X2, nullptr, nullptr);
    ln_k<<<M_,256>>>(T2, ENC, ln2g, ln2b);

    // decoder precompute
    gemm_k<EPI_NONE><<<gG4,256>>>(tgt_seq, lWx, XWX, M_, G4_, POSE_, nullptr, nullptr, nullptr, nullptr);
    gemm_k<EPI_BIAS><<<gP,256>>>(ENC, outW + (size_t)HID_*POSE_, ENCP, M_, POSE_, D_, outb, nullptr, nullptr, nullptr);
    pack_whb_k<<<(GATEB_*4*64*32+255)/256,256>>>(lWh, WHB);
    pack_wxb_k<<<(GATEB_*4*18*32+255)/256,256>>>(lWx, WXB);
    pack_owb_k<<<(OGRP_*64*32+255)/256,256>>>(outW, OWB);
    init_dec_k<<<(HBTOT_+255)/256,256>>>(vec_h, HB);

    dec_k<<<NB_,128,50688>>>(WHB, WXB, OWB, lb, XWX, ENCP, vec_c, dec0, HB, out, ep);
}